// round 7
// baseline (speedup 1.0000x reference)
#include <cuda_runtime.h>
#include <cuda_bf16.h>

// NonSparsePLIF: v[t] = where(v[t-1]*d + x[t] >= 1.0, 0, v[t-1]*d + x[t])
// x_seq [T=16, 4194304] f32, decay [1] f32.
//
// FINAL (R4 configuration — empirically best of 6 variants):
//   1 float4 per thread, block=256, grid=4096, plain loads, __stcs stores.
//   76.4us kernel, DRAM 79.8% (6323 GB/s). This is the mixed read/write HBM
//   roofline: 512 MB mandatory traffic, no reuse possible (working set >> L2),
//   T-scan carried in registers. MLP/occupancy/persistence/burst variants all
//   measured neutral or worse (76.4-79.9us band).

#define T_STEPS 16
#define SPATIAL 4194304            // 16*64*64*64
#define SPATIAL4 (SPATIAL / 4)     // float4 elements per timestep plane
#define VTH 1.0f

__global__ __launch_bounds__(256) void plif_kernel(
    const float4* __restrict__ x,      // [T, SPATIAL4]
    const float* __restrict__ decay,   // [1]
    float4* __restrict__ out)          // [T, SPATIAL4]
{
    const int i = blockIdx.x * blockDim.x + threadIdx.x;
    if (i >= SPATIAL4) return;

    const float d = decay[0];

    float4 v = make_float4(0.f, 0.f, 0.f, 0.f);

#pragma unroll
    for (int t = 0; t < T_STEPS; ++t) {
        const size_t idx = (size_t)t * SPATIAL4 + i;
        const float4 xt = x[idx];
        v.x = fmaf(v.x, d, xt.x);
        v.y = fmaf(v.y, d, xt.y);
        v.z = fmaf(v.z, d, xt.z);
        v.w = fmaf(v.w, d, xt.w);
        v.x = (v.x >= VTH) ? 0.f : v.x;
        v.y = (v.y >= VTH) ? 0.f : v.y;
        v.z = (v.z >= VTH) ? 0.f : v.z;
        v.w = (v.w >= VTH) ? 0.f : v.w;
        __stcs(&out[idx], v);   // write-once output: evict-first in L2
    }
}

extern "C" void kernel_launch(void* const* d_in, const int* in_sizes, int n_in,
                              void* d_out, int out_size)
{
    const float4* x   = (const float4*)d_in[0];
    const float*  dec = (const float*)d_in[1];
    float4*       out = (float4*)d_out;

    const int threads = 256;
    const int blocks  = (SPATIAL4 + threads - 1) / threads;  // 4096
    plif_kernel<<<blocks, threads>>>(x, dec, out);
}